// round 7
// baseline (speedup 1.0000x reference)
#include <cuda_runtime.h>
#include <cstdint>

#define B_DIM 512
#define IN_DIM 512
#define OUT_DIM 1024
#define TM 32
#define TN 64
#define TK 32
#define NSPLIT 2
#define KSPL (IN_DIM / NSPLIT)   // 256 k per split

// Tropical (min-plus) matmul: out[m, n] = min_k (x[m,k] + w[n,k])
// x: [512, 512], w: [1024, 512], out: [512, 1024], row-major fp32.
//
// K-split-2 two-stage scheme:
//   Stage 1: grid (16,16,2) = 512 CTAs; CTA (bx,by,bz) computes
//            partial[bz][m-tile][n-tile] = min over k in its half of K.
//            512 CTAs -> ~13.8 warps/SM (vs 6.9 before) for latency hiding.
//   Stage 2: combine kernel, out = min(partial[0], partial[1]).
// Scratch is a static __device__ array (no allocation).
//
// CTA tile 32(m) x 64(n), 128 threads, 4x4 register tile per thread.
// Double-buffered XOR-swizzled k-major smem tiles (col = row ^ (k & 28)),
// one barrier per k-tile, register-prefetched global loads, packed
// add.rn.f32x2 adds (bit-identical to scalar FADD), scalar FMNMX mins.

__device__ float g_partial[NSPLIT][B_DIM][OUT_DIM];   // 4 MB static scratch

__device__ __forceinline__ unsigned long long pack2(float lo, float hi) {
    unsigned long long r;
    asm("mov.b64 %0, {%1, %2};" : "=l"(r) : "r"(__float_as_uint(lo)), "r"(__float_as_uint(hi)));
    return r;
}
__device__ __forceinline__ unsigned long long addf32x2(unsigned long long a, unsigned long long b) {
    unsigned long long r;
    asm("add.rn.f32x2 %0, %1, %2;" : "=l"(r) : "l"(a), "l"(b));
    return r;
}
__device__ __forceinline__ void unpack2(unsigned long long v, float& lo, float& hi) {
    uint32_t l, h;
    asm("mov.b64 {%0, %1}, %2;" : "=r"(l), "=r"(h) : "l"(v));
    lo = __uint_as_float(l);
    hi = __uint_as_float(h);
}

__global__ __launch_bounds__(128, 4)
void tropical_mm_stage1(const float* __restrict__ x,
                        const float* __restrict__ w)
{
    __shared__ float xs[2][TK][TM];  // xs[p][k][m ^ (k&28)]
    __shared__ float ws[2][TK][TN];  // ws[p][k][n ^ (k&28)]

    const int tid = threadIdx.x;
    const int tx = tid & 15;      // n-group: 4 outputs -> 64
    const int ty = tid >> 4;      // m-group: 4 outputs -> 32
    const int m0 = blockIdx.y * TM;
    const int n0 = blockIdx.x * TN;
    const int kb = blockIdx.z * KSPL;

    // Cooperative-load coords (float4 granularity)
    const int lr = tid >> 3;         // 0..15
    const int lk = (tid & 7) << 2;   // 0,4,...,28

    const float* xg0 = &x[(m0 + lr) * IN_DIM + kb + lk];
    const float* wg0 = &w[(n0 + lr) * IN_DIM + kb + lk];

    const float INF = __int_as_float(0x7f800000);
    float acc[4][4];
#pragma unroll
    for (int i = 0; i < 4; i++)
#pragma unroll
        for (int j = 0; j < 4; j++) acc[i][j] = INF;

    // Prologue: first tile into registers
    float4 xa0 = *reinterpret_cast<const float4*>(xg0);
    float4 xa1 = *reinterpret_cast<const float4*>(xg0 + 16 * IN_DIM);
    float4 wa0 = *reinterpret_cast<const float4*>(wg0);
    float4 wa1 = *reinterpret_cast<const float4*>(wg0 + 16 * IN_DIM);
    float4 wa2 = *reinterpret_cast<const float4*>(wg0 + 32 * IN_DIM);
    float4 wa3 = *reinterpret_cast<const float4*>(wg0 + 48 * IN_DIM);

    int p = 0;
    for (int k0 = 0; k0 < KSPL; k0 += TK) {
        // STS current tile (swizzled, conflict-free). Columns computed as
        // (row ^ lk) directly — NO additive shortcuts (see R3 bug).
        {
            int x0c = (lr +  0) ^ lk;
            int x1c = (lr + 16) ^ lk;
#pragma unroll
            for (int j = 0; j < 4; j++) {
                xs[p][lk + j][x0c] = (&xa0.x)[j];
                xs[p][lk + j][x1c] = (&xa1.x)[j];
            }
            int w0c = (lr +  0) ^ lk;
            int w1c = (lr + 16) ^ lk;
            int w2c = (lr + 32) ^ lk;
            int w3c = (lr + 48) ^ lk;
#pragma unroll
            for (int j = 0; j < 4; j++) {
                ws[p][lk + j][w0c] = (&wa0.x)[j];
                ws[p][lk + j][w1c] = (&wa1.x)[j];
                ws[p][lk + j][w2c] = (&wa2.x)[j];
                ws[p][lk + j][w3c] = (&wa3.x)[j];
            }
        }
        __syncthreads();

        // Prefetch next tile (overlaps the 32-k compute loop)
        if (k0 + TK < KSPL) {
            xg0 += TK; wg0 += TK;
            xa0 = *reinterpret_cast<const float4*>(xg0);
            xa1 = *reinterpret_cast<const float4*>(xg0 + 16 * IN_DIM);
            wa0 = *reinterpret_cast<const float4*>(wg0);
            wa1 = *reinterpret_cast<const float4*>(wg0 + 16 * IN_DIM);
            wa2 = *reinterpret_cast<const float4*>(wg0 + 32 * IN_DIM);
            wa3 = *reinterpret_cast<const float4*>(wg0 + 48 * IN_DIM);
        }

        // Compute: 8 k-classes x 4 k each; base pointers computed once per
        // class, inner LDS are [Rbase + immediate].
#pragma unroll
        for (int i = 0; i < 8; i++) {
            const float* xp = &xs[p][i << 2][(ty << 2) ^ (i << 2)];
            const float* wp = &ws[p][i << 2][(tx << 2) ^ (i << 2)];
#pragma unroll
            for (int kk = 0; kk < 4; kk++) {
                float4 xv = *reinterpret_cast<const float4*>(xp + kk * TM);
                float4 wv = *reinterpret_cast<const float4*>(wp + kk * TN);
                unsigned long long w01 = pack2(wv.x, wv.y);
                unsigned long long w23 = pack2(wv.z, wv.w);
#pragma unroll
                for (int a = 0; a < 4; a++) {
                    float xa = (&xv.x)[a];
                    unsigned long long xd = pack2(xa, xa);
                    unsigned long long s01 = addf32x2(xd, w01);
                    unsigned long long s23 = addf32x2(xd, w23);
                    float s0, s1, s2, s3;
                    unpack2(s01, s0, s1);
                    unpack2(s23, s2, s3);
                    acc[a][0] = fminf(acc[a][0], s0);
                    acc[a][1] = fminf(acc[a][1], s1);
                    acc[a][2] = fminf(acc[a][2], s2);
                    acc[a][3] = fminf(acc[a][3], s3);
                }
            }
        }
        p ^= 1;
        // Single barrier per tile: nobody can overwrite buffer q before
        // passing the next tile's barrier, by which time all threads have
        // finished computing from q.
    }

    // Epilogue: partials to scratch, 4 rows of float4 per thread
    float* dst = &g_partial[blockIdx.z][0][0];
#pragma unroll
    for (int i = 0; i < 4; i++) {
        float4 o = make_float4(acc[i][0], acc[i][1], acc[i][2], acc[i][3]);
        *reinterpret_cast<float4*>(&dst[(m0 + (ty << 2) + i) * OUT_DIM + n0 + (tx << 2)]) = o;
    }
}

// Stage 2: out = elementwise min of the two partials (L2-resident traffic).
__global__ __launch_bounds__(256)
void tropical_mm_combine(float* __restrict__ out)
{
    int i = blockIdx.x * blockDim.x + threadIdx.x;   // float4 index
    const float4* p0 = reinterpret_cast<const float4*>(&g_partial[0][0][0]);
    const float4* p1 = reinterpret_cast<const float4*>(&g_partial[1][0][0]);
    float4 a = p0[i];
    float4 b = p1[i];
    float4 r = make_float4(fminf(a.x, b.x), fminf(a.y, b.y),
                           fminf(a.z, b.z), fminf(a.w, b.w));
    reinterpret_cast<float4*>(out)[i] = r;
}

extern "C" void kernel_launch(void* const* d_in, const int* in_sizes, int n_in,
                              void* d_out, int out_size)
{
    const float* x = (const float*)d_in[0];   // [512, 512]
    const float* w = (const float*)d_in[1];   // [1024, 512]
    float* out = (float*)d_out;               // [512, 1024]

    dim3 grid1(OUT_DIM / TN, B_DIM / TM, NSPLIT);   // (16, 16, 2) = 512 CTAs
    tropical_mm_stage1<<<grid1, 128>>>(x, w);

    int n4 = B_DIM * OUT_DIM / 4;                   // 131072 float4
    tropical_mm_combine<<<n4 / 256, 256>>>(out);
}

// round 8
// speedup vs baseline: 1.0106x; 1.0106x over previous
#include <cuda_runtime.h>
#include <cstdint>

#define B_DIM 512
#define IN_DIM 512
#define OUT_DIM 1024
#define TM 32
#define TN 64
#define TK 32
#define NSPLIT 2
#define KSPL (IN_DIM / NSPLIT)   // 256 k per split

// Tropical (min-plus) matmul: out[m, n] = min_k (x[m,k] + w[n,k])
// x: [512, 512], w: [1024, 512], out: [512, 1024], row-major fp32.
//
// K-split-2 fused via 2-CTA clusters: cluster = the two CTAs computing the
// same 32x64 output tile over different K-halves. Rank 1 ships its 16
// accumulators/thread to rank 0 through DSMEM; rank 0 combines and writes
// the final output. No scratch buffer, no combine kernel.
//
// CTA tile 32(m) x 64(n), 128 threads, 4x4 register tile per thread.
// Grid (2,16,16) = 512 CTAs (~14 warps/SM). Double-buffered XOR-swizzled
// k-major smem tiles (col = row ^ (k & 28)), one barrier per k-tile,
// register-prefetched global loads, packed add.rn.f32x2 adds (bit-identical
// to scalar FADD), scalar FMNMX mins.

__device__ __forceinline__ unsigned long long pack2(float lo, float hi) {
    unsigned long long r;
    asm("mov.b64 %0, {%1, %2};" : "=l"(r) : "r"(__float_as_uint(lo)), "r"(__float_as_uint(hi)));
    return r;
}
__device__ __forceinline__ unsigned long long addf32x2(unsigned long long a, unsigned long long b) {
    unsigned long long r;
    asm("add.rn.f32x2 %0, %1, %2;" : "=l"(r) : "l"(a), "l"(b));
    return r;
}
__device__ __forceinline__ void unpack2(unsigned long long v, float& lo, float& hi) {
    uint32_t l, h;
    asm("mov.b64 {%0, %1}, %2;" : "=r"(l), "=r"(h) : "l"(v));
    lo = __uint_as_float(l);
    hi = __uint_as_float(h);
}
__device__ __forceinline__ uint32_t smem_u32(const void* p) {
    uint32_t a;
    asm("{ .reg .u64 t; cvta.to.shared.u64 t, %1; cvt.u32.u64 %0, t; }" : "=r"(a) : "l"(p));
    return a;
}
__device__ __forceinline__ uint32_t mapa_rank(uint32_t local, uint32_t rank) {
    uint32_t r;
    asm("mapa.shared::cluster.u32 %0, %1, %2;" : "=r"(r) : "r"(local), "r"(rank));
    return r;
}
__device__ __forceinline__ float dsmem_ld_f32(uint32_t addr) {
    float v;
    asm volatile("ld.shared::cluster.f32 %0, [%1];" : "=f"(v) : "r"(addr));
    return v;
}

__global__ __launch_bounds__(128, 4) __cluster_dims__(NSPLIT, 1, 1)
void tropical_mm_kernel(const float* __restrict__ x,
                        const float* __restrict__ w,
                        float* __restrict__ out)
{
    __shared__ float xs[2][TK][TM];   // xs[p][k][m ^ (k&28)]
    __shared__ float ws[2][TK][TN];   // ws[p][k][n ^ (k&28)]
    __shared__ float red[16][128];    // rank-1 accumulator handoff (8 KB)

    const int tid = threadIdx.x;
    const int tx = tid & 15;      // n-group: 4 outputs -> 64
    const int ty = tid >> 4;      // m-group: 4 outputs -> 32
    const int rank = blockIdx.x;  // split index == cluster CTA rank (x fastest)
    const int n0 = blockIdx.y * TN;
    const int m0 = blockIdx.z * TM;
    const int kb = rank * KSPL;

    // Cooperative-load coords (float4 granularity)
    const int lr = tid >> 3;         // 0..15
    const int lk = (tid & 7) << 2;   // 0,4,...,28

    const float* xg0 = &x[(m0 + lr) * IN_DIM + kb + lk];
    const float* wg0 = &w[(n0 + lr) * IN_DIM + kb + lk];

    const float INF = __int_as_float(0x7f800000);
    float acc[4][4];
#pragma unroll
    for (int i = 0; i < 4; i++)
#pragma unroll
        for (int j = 0; j < 4; j++) acc[i][j] = INF;

    // Prologue: first tile into registers
    float4 xa0 = *reinterpret_cast<const float4*>(xg0);
    float4 xa1 = *reinterpret_cast<const float4*>(xg0 + 16 * IN_DIM);
    float4 wa0 = *reinterpret_cast<const float4*>(wg0);
    float4 wa1 = *reinterpret_cast<const float4*>(wg0 + 16 * IN_DIM);
    float4 wa2 = *reinterpret_cast<const float4*>(wg0 + 32 * IN_DIM);
    float4 wa3 = *reinterpret_cast<const float4*>(wg0 + 48 * IN_DIM);

    int p = 0;
    for (int k0 = 0; k0 < KSPL; k0 += TK) {
        // STS current tile (swizzled, conflict-free). Columns computed as
        // (row ^ lk) directly — NO additive shortcuts (see R3 bug).
        {
            int x0c = (lr +  0) ^ lk;
            int x1c = (lr + 16) ^ lk;
#pragma unroll
            for (int j = 0; j < 4; j++) {
                xs[p][lk + j][x0c] = (&xa0.x)[j];
                xs[p][lk + j][x1c] = (&xa1.x)[j];
            }
            int w0c = (lr +  0) ^ lk;
            int w1c = (lr + 16) ^ lk;
            int w2c = (lr + 32) ^ lk;
            int w3c = (lr + 48) ^ lk;
#pragma unroll
            for (int j = 0; j < 4; j++) {
                ws[p][lk + j][w0c] = (&wa0.x)[j];
                ws[p][lk + j][w1c] = (&wa1.x)[j];
                ws[p][lk + j][w2c] = (&wa2.x)[j];
                ws[p][lk + j][w3c] = (&wa3.x)[j];
            }
        }
        __syncthreads();

        // Prefetch next tile (overlaps the 32-k compute loop)
        if (k0 + TK < KSPL) {
            xg0 += TK; wg0 += TK;
            xa0 = *reinterpret_cast<const float4*>(xg0);
            xa1 = *reinterpret_cast<const float4*>(xg0 + 16 * IN_DIM);
            wa0 = *reinterpret_cast<const float4*>(wg0);
            wa1 = *reinterpret_cast<const float4*>(wg0 + 16 * IN_DIM);
            wa2 = *reinterpret_cast<const float4*>(wg0 + 32 * IN_DIM);
            wa3 = *reinterpret_cast<const float4*>(wg0 + 48 * IN_DIM);
        }

        // Compute: 8 k-classes x 4 k each; base pointers computed once per
        // class, inner LDS are [Rbase + immediate].
#pragma unroll
        for (int i = 0; i < 8; i++) {
            const float* xp = &xs[p][i << 2][(ty << 2) ^ (i << 2)];
            const float* wp = &ws[p][i << 2][(tx << 2) ^ (i << 2)];
#pragma unroll
            for (int kk = 0; kk < 4; kk++) {
                float4 xv = *reinterpret_cast<const float4*>(xp + kk * TM);
                float4 wv = *reinterpret_cast<const float4*>(wp + kk * TN);
                unsigned long long w01 = pack2(wv.x, wv.y);
                unsigned long long w23 = pack2(wv.z, wv.w);
#pragma unroll
                for (int a = 0; a < 4; a++) {
                    float xa = (&xv.x)[a];
                    unsigned long long xd = pack2(xa, xa);
                    unsigned long long s01 = addf32x2(xd, w01);
                    unsigned long long s23 = addf32x2(xd, w23);
                    float s0, s1, s2, s3;
                    unpack2(s01, s0, s1);
                    unpack2(s23, s2, s3);
                    acc[a][0] = fminf(acc[a][0], s0);
                    acc[a][1] = fminf(acc[a][1], s1);
                    acc[a][2] = fminf(acc[a][2], s2);
                    acc[a][3] = fminf(acc[a][3], s3);
                }
            }
        }
        p ^= 1;
        // Single barrier per tile: nobody can overwrite buffer q before
        // passing the next tile's barrier, by which time all threads have
        // finished computing from q.
    }

    // ── Cluster epilogue: rank 1 -> rank 0 handoff, rank 0 writes out ──
    if (rank == 1) {
#pragma unroll
        for (int i = 0; i < 4; i++)
#pragma unroll
            for (int j = 0; j < 4; j++)
                red[(i << 2) + j][tid] = acc[i][j];
    }
    // barrier.cluster.arrive has release semantics (orders the STS above);
    // wait has acquire (orders the DSMEM reads below).
    asm volatile("barrier.cluster.arrive.aligned;" ::: "memory");
    asm volatile("barrier.cluster.wait.aligned;"   ::: "memory");

    if (rank == 0) {
        uint32_t rbase = mapa_rank(smem_u32(&red[0][0]), 1) + tid * 4;
#pragma unroll
        for (int i = 0; i < 4; i++) {
#pragma unroll
            for (int j = 0; j < 4; j++) {
                float pv = dsmem_ld_f32(rbase + ((i << 2) + j) * 128 * 4);
                acc[i][j] = fminf(acc[i][j], pv);
            }
            float4 o = make_float4(acc[i][0], acc[i][1], acc[i][2], acc[i][3]);
            *reinterpret_cast<float4*>(
                &out[(m0 + (ty << 2) + i) * OUT_DIM + n0 + (tx << 2)]) = o;
        }
    }

    // Keep rank 1's smem alive until rank 0 has finished reading it.
    asm volatile("barrier.cluster.arrive.aligned;" ::: "memory");
    asm volatile("barrier.cluster.wait.aligned;"   ::: "memory");
}

extern "C" void kernel_launch(void* const* d_in, const int* in_sizes, int n_in,
                              void* d_out, int out_size)
{
    const float* x = (const float*)d_in[0];   // [512, 512]
    const float* w = (const float*)d_in[1];   // [1024, 512]
    float* out = (float*)d_out;               // [512, 1024]

    dim3 grid(NSPLIT, OUT_DIM / TN, B_DIM / TM);   // (2, 16, 16) = 512 CTAs
    tropical_mm_kernel<<<grid, 128>>>(x, w, out);
}